// round 14
// baseline (speedup 1.0000x reference)
#include <cuda_runtime.h>
#include <cuda_bf16.h>
#include <cuda_fp16.h>
#include <cstdint>

#define N_NODES 100000
#define F_DIM   256
#define E_DIM   128
#define B_DIM   8192
#define D_DIM   32
#define K_SEL   16
#define CAT_DIM 640   // F + 3E

// ---------------------------------------------------------------------------
// Scratch (static device globals — no allocations allowed)
// ---------------------------------------------------------------------------
__device__ __align__(16) float          g_scores[N_NODES * 2];
__device__ __align__(16) __half         g_feat_h[(size_t)N_NODES * F_DIM];  // fp16 features
__device__ __align__(16) __nv_bfloat16  g_mean_hi[3ULL * B_DIM * F_DIM];   // [r][m][k]
__device__ __align__(16) __nv_bfloat16  g_mean_lo[3ULL * B_DIM * F_DIM];
__device__ __align__(16) __nv_bfloat16  g_cat_hi[(size_t)B_DIM * CAT_DIM]; // [m][k]
__device__ __align__(16) __nv_bfloat16  g_cat_lo[(size_t)B_DIM * CAT_DIM];
__device__ __align__(16) __nv_bfloat16  g_w_hi[3 * F_DIM * E_DIM];         // [r][k][n]
__device__ __align__(16) __nv_bfloat16  g_w_lo[3 * F_DIM * E_DIM];
__device__ __align__(16) __nv_bfloat16  g_wgt_hi[CAT_DIM * E_DIM];         // [k][n]
__device__ __align__(16) __nv_bfloat16  g_wgt_lo[CAT_DIM * E_DIM];

// ---------------------------------------------------------------------------
// helpers
// ---------------------------------------------------------------------------
__device__ __forceinline__ uint32_t smem_u32(const void* p) {
    uint32_t a;
    asm("{ .reg .u64 t; cvta.to.shared.u64 t, %1; cvt.u32.u64 %0, t; }" : "=r"(a) : "l"(p));
    return a;
}
__device__ __forceinline__ void bf16split(float x, __nv_bfloat16& h, __nv_bfloat16& l) {
    h = __float2bfloat16(x);
    l = __float2bfloat16(x - __bfloat162float(h));
}
__device__ __forceinline__ uint32_t pack2(__nv_bfloat16 a, __nv_bfloat16 b) {
    __nv_bfloat162 t = __halves2bfloat162(a, b);
    return *reinterpret_cast<uint32_t*>(&t);
}
__device__ __forceinline__ uint32_t packh2(float a, float b) {
    __half2 t = __floats2half2_rn(a, b);
    return *reinterpret_cast<uint32_t*>(&t);
}
__device__ __forceinline__ void ldsm4(uint32_t* r, uint32_t addr) {
    asm volatile("ldmatrix.sync.aligned.m8n8.x4.shared.b16 {%0,%1,%2,%3}, [%4];"
                 : "=r"(r[0]), "=r"(r[1]), "=r"(r[2]), "=r"(r[3]) : "r"(addr));
}
__device__ __forceinline__ void ldsm4t(uint32_t* r, uint32_t addr) {
    asm volatile("ldmatrix.sync.aligned.m8n8.x4.trans.shared.b16 {%0,%1,%2,%3}, [%4];"
                 : "=r"(r[0]), "=r"(r[1]), "=r"(r[2]), "=r"(r[3]) : "r"(addr));
}
__device__ __forceinline__ void mma16816(float* c, const uint32_t* a, const uint32_t* b) {
    asm volatile(
        "mma.sync.aligned.m16n8k16.row.col.f32.bf16.bf16.f32 "
        "{%0,%1,%2,%3}, {%4,%5,%6,%7}, {%8,%9}, {%0,%1,%2,%3};"
        : "+f"(c[0]), "+f"(c[1]), "+f"(c[2]), "+f"(c[3])
        : "r"(a[0]), "r"(a[1]), "r"(a[2]), "r"(a[3]), "r"(b[0]), "r"(b[1]));
}
__device__ __forceinline__ void cp16(uint32_t s, const void* g) {
    asm volatile("cp.async.cg.shared.global [%0], [%1], 16;" :: "r"(s), "l"(g));
}
#define CP_COMMIT() asm volatile("cp.async.commit_group;" ::: "memory")
#define CP_WAIT(n)  asm volatile("cp.async.wait_group %0;" :: "n"(n) : "memory")

// ---------------------------------------------------------------------------
// K1: scores[n] = features[n] @ wc + bc (one warp per node)
//     + vectorized fp16 feature copy (lane owns 8 contiguous cols)
// ---------------------------------------------------------------------------
__global__ void k_scores(const float* __restrict__ feat, const float* __restrict__ wc,
                         const float* __restrict__ bc) {
    int gwarp = (blockIdx.x * blockDim.x + threadIdx.x) >> 5;
    int lane  = threadIdx.x & 31;
    if (gwarp >= N_NODES) return;
    const float* row = feat + (size_t)gwarp * F_DIM;
    int f0 = lane * 8;
    float4 va = *(const float4*)(row + f0);
    float4 vb = *(const float4*)(row + f0 + 4);
    float v[8] = { va.x, va.y, va.z, va.w, vb.x, vb.y, vb.z, vb.w };
    float s0 = 0.f, s1 = 0.f;
#pragma unroll
    for (int q = 0; q < 8; q++) {
        s0 += v[q] * __ldg(&wc[(f0 + q) * 2 + 0]);
        s1 += v[q] * __ldg(&wc[(f0 + q) * 2 + 1]);
    }
    uint4 h;
    h.x = packh2(v[0], v[1]); h.y = packh2(v[2], v[3]);
    h.z = packh2(v[4], v[5]); h.w = packh2(v[6], v[7]);
    *(uint4*)(g_feat_h + (size_t)gwarp * F_DIM + f0) = h;
#pragma unroll
    for (int o = 16; o; o >>= 1) {
        s0 += __shfl_down_sync(0xFFFFFFFFu, s0, o);
        s1 += __shfl_down_sync(0xFFFFFFFFu, s1, o);
    }
    if (lane == 0) {
        g_scores[gwarp * 2 + 0] = s0 + bc[0];
        g_scores[gwarp * 2 + 1] = s1 + bc[1];
    }
}

// ---------------------------------------------------------------------------
// K2: self features -> g_cat cols [0,256) + center scores (4 rows / block)
//     (reads fp32 features: exact self-path, bf16 hi/lo split out)
// ---------------------------------------------------------------------------
__global__ void k_self(const float* __restrict__ feat, const int* __restrict__ nodes,
                       float* __restrict__ out_center) {
    int b = blockIdx.x * 4 + (threadIdx.x >> 6);
    int t = threadIdx.x & 63;
    int node = nodes[b];
    float4 v = *(const float4*)(feat + (size_t)node * F_DIM + 4 * t);
    __nv_bfloat16 h0, h1, h2, h3, l0, l1, l2, l3;
    bf16split(v.x, h0, l0); bf16split(v.y, h1, l1);
    bf16split(v.z, h2, l2); bf16split(v.w, h3, l3);
    size_t base = (size_t)b * CAT_DIM + 4 * t;
    uint2 ph, pl;
    ph.x = pack2(h0, h1); ph.y = pack2(h2, h3);
    pl.x = pack2(l0, l1); pl.y = pack2(l2, l3);
    *(uint2*)(g_cat_hi + base) = ph;
    *(uint2*)(g_cat_lo + base) = pl;
    if (t < 2) out_center[b * 2 + t] = g_scores[node * 2 + t];
}

// ---------------------------------------------------------------------------
// K3: stable top-K=16 by |s1-c| (fp32 scores, warp-shuffle rank — identical
// selection), gather-mean from fp16 copy with LDG.128 (lane owns 8 cols),
// fp32 accumulate, bf16 hi/lo split out. 2 warps/block, 1 b per warp.
// ---------------------------------------------------------------------------
__global__ void k_relsum(const int* __restrict__ nodes,
                         const int* __restrict__ n1, const int* __restrict__ n2,
                         const int* __restrict__ n3) {
    int w    = threadIdx.x >> 5;
    int lane = threadIdx.x & 31;
    int b    = blockIdx.x * 2 + w;
    int r    = blockIdx.y;

    __shared__ int s_sel[2][K_SEL];

    const int* nb = (r == 0 ? n1 : (r == 1 ? n2 : n3)) + (size_t)b * D_DIM;
    int   nv = nb[lane];
    float c  = g_scores[nodes[b] * 2 + 1];
    float d  = fabsf(g_scores[nv * 2 + 1] - c);
    int rank = 0;
#pragma unroll
    for (int j = 0; j < 32; j++) {
        float dj = __shfl_sync(0xFFFFFFFFu, d, j);
        rank += (dj < d) || (dj == d && j < lane);   // stable: matches jax top_k
    }
    if (rank < K_SEL) s_sel[w][rank] = nv;
    __syncwarp();

    int sel[K_SEL];
#pragma unroll
    for (int k = 0; k < K_SEL; k++) sel[k] = s_sel[w][k];

    float acc[8] = {0.f, 0.f, 0.f, 0.f, 0.f, 0.f, 0.f, 0.f};
#pragma unroll
    for (int k = 0; k < K_SEL; k++) {
        uint4 u = *(const uint4*)(g_feat_h + (size_t)sel[k] * F_DIM + lane * 8);
        float2 f0 = __half22float2(*reinterpret_cast<__half2*>(&u.x));
        float2 f1 = __half22float2(*reinterpret_cast<__half2*>(&u.y));
        float2 f2 = __half22float2(*reinterpret_cast<__half2*>(&u.z));
        float2 f3 = __half22float2(*reinterpret_cast<__half2*>(&u.w));
        acc[0] += f0.x; acc[1] += f0.y; acc[2] += f1.x; acc[3] += f1.y;
        acc[4] += f2.x; acc[5] += f2.y; acc[6] += f3.x; acc[7] += f3.y;
    }
    const float s = 1.0f / K_SEL;
    __nv_bfloat16 hh[8], ll[8];
#pragma unroll
    for (int q = 0; q < 8; q++) bf16split(acc[q] * s, hh[q], ll[q]);
    uint4 ph, pl;
    ph.x = pack2(hh[0], hh[1]); ph.y = pack2(hh[2], hh[3]);
    ph.z = pack2(hh[4], hh[5]); ph.w = pack2(hh[6], hh[7]);
    pl.x = pack2(ll[0], ll[1]); pl.y = pack2(ll[2], ll[3]);
    pl.z = pack2(ll[4], ll[5]); pl.w = pack2(ll[6], ll[7]);
    size_t base = ((size_t)r * B_DIM + b) * F_DIM + lane * 8;
    *(uint4*)(g_mean_hi + base) = ph;
    *(uint4*)(g_mean_lo + base) = pl;
}

// ---------------------------------------------------------------------------
// K_prep: bf16-split weights (already [K][N] layout — no transpose)
// ---------------------------------------------------------------------------
__global__ void k_prep(const float* __restrict__ w1, const float* __restrict__ w2,
                       const float* __restrict__ w3, const float* __restrict__ weight) {
    int idx = blockIdx.x * blockDim.x + threadIdx.x;
    const int NW = 3 * F_DIM * E_DIM;   // 98304
    const int NG = CAT_DIM * E_DIM;     // 81920
    if (idx < NW) {
        int r = idx >> 15;
        const float* w = (r == 0 ? w1 : (r == 1 ? w2 : w3));
        float v = w[idx & 32767];
        __nv_bfloat16 h, l; bf16split(v, h, l);
        g_w_hi[idx] = h; g_w_lo[idx] = l;
    } else if (idx < NW + NG) {
        int j = idx - NW;
        float v = weight[j];
        __nv_bfloat16 h, l; bf16split(v, h, l);
        g_wgt_hi[j] = h; g_wgt_lo[j] = l;
    }
}

// ---------------------------------------------------------------------------
// HMMA GEMM, cp.async 2-stage single-sync pipeline (R9/R11-measured, bf16
// 3-term split: Ah*Bh + Ah*Bl + Al*Bh, fp32 accum). 8 warps = 2m x 4n.
// mode 0 (BN=128): blockIdx.y = relation; relu -> bf16 split -> g_cat cols.
// mode 1 (BN=64):  blockIdx.y = n-half;  relu -> out.T
// ---------------------------------------------------------------------------
#define PA 144        // A row pitch bytes (64 bf16 + 16B pad)
#define BM 64
#define SA_SZ (BM * PA)

template<int BN>
__global__ void __launch_bounds__(256, 2)
k_gemm(const __nv_bfloat16* __restrict__ Ah, const __nv_bfloat16* __restrict__ Al,
       const __nv_bfloat16* __restrict__ Bh, const __nv_bfloat16* __restrict__ Bl,
       int K, int mode, float* __restrict__ out) {
    constexpr int JN   = BN / 32;          // 8-col n fragments per warp
    constexpr int PBn  = BN * 2 + 16;      // B row pitch bytes
    constexpr int SBT  = 64 * PBn;
    constexpr int STG  = 2 * SA_SZ + 2 * SBT;

    extern __shared__ char smem[];
    uint32_t sb = smem_u32(smem);

    int tid  = threadIdx.x;
    int lane = tid & 31;
    int warp = tid >> 5;
    int wm   = warp & 1;      // 2 warps along m
    int wn   = warp >> 1;     // 4 warps along n
    int m0   = blockIdx.x * BM;
    int colbase = 0;          // mode 0: g_cat col base; mode 1: out n base

    if (mode == 0) {
        int r = blockIdx.y;
        Ah += (size_t)r * B_DIM * K;
        Al += (size_t)r * B_DIM * K;
        Bh += (size_t)r * K * E_DIM;
        Bl += (size_t)r * K * E_DIM;
        colbase = F_DIM + r * E_DIM;
    } else {
        int nb = blockIdx.y * BN;
        Bh += nb;  Bl += nb;
        colbase = nb;
    }
    const __nv_bfloat16* At_h = Ah + (size_t)m0 * K;
    const __nv_bfloat16* At_l = Al + (size_t)m0 * K;

    uint32_t aoff = (wm * 32 + (lane & 7) + ((lane >> 3) & 1) * 8) * PA + (lane >> 4) * 16;
    uint32_t boff = ((lane & 7) + ((lane >> 3) & 1) * 8) * PBn + (lane >> 4) * 16
                  + wn * (JN * 8) * 2;

    float c[2][JN][4];
#pragma unroll
    for (int i = 0; i < 2; i++)
#pragma unroll
        for (int j = 0; j < JN; j++)
#pragma unroll
            for (int q = 0; q < 4; q++) c[i][j][q] = 0.f;

    const int NC = K >> 6;

    auto stage_load = [&](uint32_t base, int kofs) {
#pragma unroll
        for (int u = tid; u < BM * 8; u += 256) {
            int row = u >> 3, c16 = u & 7;
            size_t go = (size_t)row * K + kofs + c16 * 8;
            uint32_t so = row * PA + c16 * 16;
            cp16(base + so,         At_h + go);
            cp16(base + SA_SZ + so, At_l + go);
        }
#pragma unroll
        for (int u = tid; u < 64 * (BN / 8); u += 256) {
            int row = u / (BN / 8), c16 = u % (BN / 8);
            size_t go = (size_t)(kofs + row) * E_DIM + c16 * 8;
            uint32_t so = row * PBn + c16 * 16;
            cp16(base + 2 * SA_SZ + so,       Bh + go);
            cp16(base + 2 * SA_SZ + SBT + so, Bl + go);
        }
    };

    stage_load(sb, 0);
    CP_COMMIT();

#pragma unroll 1
    for (int ch = 0; ch < NC; ch++) {
        CP_WAIT(0);
        __syncthreads();
        // safe: all warps finished compute(ch-1); buffer (ch+1)&1 == (ch-1)&1 free
        if (ch + 1 < NC) {
            stage_load(sb + ((ch + 1) & 1) * STG, (ch + 1) * 64);
            CP_COMMIT();
        }

        uint32_t base = sb + (ch & 1) * STG;
#pragma unroll
        for (int s = 0; s < 4; s++) {
            uint32_t ah[2][4], al_[2][4];
#pragma unroll
            for (int i = 0; i < 2; i++) {
                ldsm4(ah[i],  base + aoff + i * 16 * PA + 32 * s);
                ldsm4(al_[i], base + SA_SZ + aoff + i * 16 * PA + 32 * s);
            }
            uint32_t bh[JN][2], bl[JN][2];
#pragma unroll
            for (int q = 0; q < JN / 2; q++) {
                uint32_t r4[4];
                ldsm4t(r4, base + 2 * SA_SZ + boff + 16 * s * PBn + q * 32);
                bh[2*q][0] = r4[0]; bh[2*q][1] = r4[1];
                bh[2*q+1][0] = r4[2]; bh[2*q+1][1] = r4[3];
                ldsm4t(r4, base + 2 * SA_SZ + SBT + boff + 16 * s * PBn + q * 32);
                bl[2*q][0] = r4[0]; bl[2*q][1] = r4[1];
                bl[2*q+1][0] = r4[2]; bl[2*q+1][1] = r4[3];
            }
#pragma unroll
            for (int i = 0; i < 2; i++)
#pragma unroll
                for (int j = 0; j < JN; j++) {
                    mma16816(c[i][j], ah[i],  bh[j]);
                    mma16816(c[i][j], ah[i],  bl[j]);
                    mma16816(c[i][j], al_[i], bh[j]);
                }
        }
    }

    int g  = lane >> 2;
    int tg = lane & 3;
#pragma unroll
    for (int i = 0; i < 2; i++) {
#pragma unroll
        for (int j = 0; j < JN; j++) {
            int m = m0 + wm * 32 + i * 16 + g;
            int n = colbase + wn * (JN * 8) + j * 8 + tg * 2;
            float x0 = fmaxf(c[i][j][0], 0.f);
            float x1 = fmaxf(c[i][j][1], 0.f);
            float x2 = fmaxf(c[i][j][2], 0.f);
            float x3 = fmaxf(c[i][j][3], 0.f);
            if (mode == 0) {
                __nv_bfloat16 h0, h1, h2, h3, l0, l1, l2, l3;
                bf16split(x0, h0, l0); bf16split(x1, h1, l1);
                bf16split(x2, h2, l2); bf16split(x3, h3, l3);
                size_t p0 = (size_t)m * CAT_DIM + n;
                size_t p1 = (size_t)(m + 8) * CAT_DIM + n;
                *(uint32_t*)(g_cat_hi + p0) = pack2(h0, h1);
                *(uint32_t*)(g_cat_lo + p0) = pack2(l0, l1);
                *(uint32_t*)(g_cat_hi + p1) = pack2(h2, h3);
                *(uint32_t*)(g_cat_lo + p1) = pack2(l2, l3);
            } else {
                out[(size_t)n * B_DIM + m]           = x0;
                out[(size_t)(n + 1) * B_DIM + m]     = x1;
                out[(size_t)n * B_DIM + m + 8]       = x2;
                out[(size_t)(n + 1) * B_DIM + m + 8] = x3;
            }
        }
    }
}

#define SMEM_G128 (2 * (2 * SA_SZ + 2 * 64 * (128 * 2 + 16)))   // 106496
#define SMEM_G64  (2 * (2 * SA_SZ + 2 * 64 * (64 * 2 + 16)))    // 73728

// ---------------------------------------------------------------------------
extern "C" void kernel_launch(void* const* d_in, const int* in_sizes, int n_in,
                              void* d_out, int out_size) {
    const float* features = (const float*)d_in[0];
    const int*   nodes    = (const int*)d_in[1];
    const int*   n1       = (const int*)d_in[2];
    const int*   n2       = (const int*)d_in[3];
    const int*   n3       = (const int*)d_in[4];
    const float* wc       = (const float*)d_in[5];
    const float* bc       = (const float*)d_in[6];
    const float* w1       = (const float*)d_in[7];
    const float* w2       = (const float*)d_in[8];
    const float* w3       = (const float*)d_in[9];
    const float* weight   = (const float*)d_in[10];

    float* out_combined = (float*)d_out;                 // 128 x 8192
    float* out_center   = (float*)d_out + E_DIM * B_DIM; // 8192 x 2

    static bool attr_done = false;
    static __nv_bfloat16 *p_mean_hi, *p_mean_lo, *p_cat_hi, *p_cat_lo;
    static __nv_bfloat16 *p_w_hi, *p_w_lo, *p_wgt_hi, *p_wgt_lo;
    if (!attr_done) {
        cudaFuncSetAttribute(k_gemm<128>, cudaFuncAttributeMaxDynamicSharedMemorySize, SMEM_G128);
        cudaFuncSetAttribute(k_gemm<64>,  cudaFuncAttributeMaxDynamicSharedMemorySize, SMEM_G64);
        cudaGetSymbolAddress((void**)&p_mean_hi, g_mean_hi);
        cudaGetSymbolAddress((void**)&p_mean_lo, g_mean_lo);
        cudaGetSymbolAddress((void**)&p_cat_hi,  g_cat_hi);
        cudaGetSymbolAddress((void**)&p_cat_lo,  g_cat_lo);
        cudaGetSymbolAddress((void**)&p_w_hi,    g_w_hi);
        cudaGetSymbolAddress((void**)&p_w_lo,    g_w_lo);
        cudaGetSymbolAddress((void**)&p_wgt_hi,  g_wgt_hi);
        cudaGetSymbolAddress((void**)&p_wgt_lo,  g_wgt_lo);
        attr_done = true;
    }

    // weights prep (independent of scores)
    k_prep<<<(3 * F_DIM * E_DIM + CAT_DIM * E_DIM + 255) / 256, 256>>>(w1, w2, w3, weight);

    // scores + vectorized fp16 feature copy
    k_scores<<<(N_NODES + 7) / 8, 256>>>(features, wc, bc);

    // self features -> cat + center scores
    k_self<<<B_DIM / 4, 256>>>(features, nodes, out_center);

    // top-K + mean features (fp16 LDG.128 gather, 2 warps/block)
    k_relsum<<<dim3(B_DIM / 2, 3), 64>>>(nodes, n1, n2, n3);

    // relation GEMMs: relu(mean @ w_r) -> cat columns (BN=128, grid 128x3)
    k_gemm<128><<<dim3(B_DIM / BM, 3), 256, SMEM_G128>>>(
        p_mean_hi, p_mean_lo, p_w_hi, p_w_lo, F_DIM, 0, out_combined);

    // final GEMM: relu(cat @ weight).T -> out (BN=64, grid 128x2 = 256 CTAs)
    k_gemm<64><<<dim3(B_DIM / BM, 2), 256, SMEM_G64>>>(
        p_cat_hi, p_cat_lo, p_wgt_hi, p_wgt_lo, CAT_DIM, 1, out_combined);
}

// round 15
// speedup vs baseline: 1.7166x; 1.7166x over previous
#include <cuda_runtime.h>
#include <cuda_bf16.h>
#include <cuda_fp16.h>
#include <cstdint>

#define N_NODES 100000
#define F_DIM   256
#define E_DIM   128
#define B_DIM   8192
#define D_DIM   32
#define K_SEL   16
#define CAT_DIM 640   // F + 3E

// ---------------------------------------------------------------------------
// Scratch (static device globals — no allocations allowed)
// ---------------------------------------------------------------------------
__device__ __align__(16) float          g_scores[N_NODES * 2];
__device__ __align__(16) __half         g_feat_h[(size_t)N_NODES * F_DIM];  // fp16 features
__device__ __align__(16) __nv_bfloat16  g_mean_hi[3ULL * B_DIM * F_DIM];   // [r][m][k]
__device__ __align__(16) __nv_bfloat16  g_mean_lo[3ULL * B_DIM * F_DIM];
__device__ __align__(16) __nv_bfloat16  g_cat_hi[(size_t)B_DIM * CAT_DIM]; // [m][k]
__device__ __align__(16) __nv_bfloat16  g_cat_lo[(size_t)B_DIM * CAT_DIM];
__device__ __align__(16) __nv_bfloat16  g_w_hi[3 * F_DIM * E_DIM];         // [r][k][n]
__device__ __align__(16) __nv_bfloat16  g_w_lo[3 * F_DIM * E_DIM];
__device__ __align__(16) __nv_bfloat16  g_wgt_hi[CAT_DIM * E_DIM];         // [k][n]
__device__ __align__(16) __nv_bfloat16  g_wgt_lo[CAT_DIM * E_DIM];

// ---------------------------------------------------------------------------
// helpers
// ---------------------------------------------------------------------------
__device__ __forceinline__ uint32_t smem_u32(const void* p) {
    uint32_t a;
    asm("{ .reg .u64 t; cvta.to.shared.u64 t, %1; cvt.u32.u64 %0, t; }" : "=r"(a) : "l"(p));
    return a;
}
__device__ __forceinline__ void bf16split(float x, __nv_bfloat16& h, __nv_bfloat16& l) {
    h = __float2bfloat16(x);
    l = __float2bfloat16(x - __bfloat162float(h));
}
__device__ __forceinline__ uint32_t pack2(__nv_bfloat16 a, __nv_bfloat16 b) {
    __nv_bfloat162 t = __halves2bfloat162(a, b);
    return *reinterpret_cast<uint32_t*>(&t);
}
__device__ __forceinline__ void ldsm4(uint32_t* r, uint32_t addr) {
    asm volatile("ldmatrix.sync.aligned.m8n8.x4.shared.b16 {%0,%1,%2,%3}, [%4];"
                 : "=r"(r[0]), "=r"(r[1]), "=r"(r[2]), "=r"(r[3]) : "r"(addr));
}
__device__ __forceinline__ void ldsm4t(uint32_t* r, uint32_t addr) {
    asm volatile("ldmatrix.sync.aligned.m8n8.x4.trans.shared.b16 {%0,%1,%2,%3}, [%4];"
                 : "=r"(r[0]), "=r"(r[1]), "=r"(r[2]), "=r"(r[3]) : "r"(addr));
}
__device__ __forceinline__ void mma16816(float* c, const uint32_t* a, const uint32_t* b) {
    asm volatile(
        "mma.sync.aligned.m16n8k16.row.col.f32.bf16.bf16.f32 "
        "{%0,%1,%2,%3}, {%4,%5,%6,%7}, {%8,%9}, {%0,%1,%2,%3};"
        : "+f"(c[0]), "+f"(c[1]), "+f"(c[2]), "+f"(c[3])
        : "r"(a[0]), "r"(a[1]), "r"(a[2]), "r"(a[3]), "r"(b[0]), "r"(b[1]));
}
__device__ __forceinline__ void cp16(uint32_t s, const void* g) {
    asm volatile("cp.async.cg.shared.global [%0], [%1], 16;" :: "r"(s), "l"(g));
}
#define CP_COMMIT() asm volatile("cp.async.commit_group;" ::: "memory")
#define CP_WAIT(n)  asm volatile("cp.async.wait_group %0;" :: "n"(n) : "memory")

// ---------------------------------------------------------------------------
// K1: scores[n] = features[n] @ wc + bc (one warp per node)
//     + fp16 copy of features (R11-measured scalar form)
// ---------------------------------------------------------------------------
__global__ void k_scores(const float* __restrict__ feat, const float* __restrict__ wc,
                         const float* __restrict__ bc) {
    int gwarp = (blockIdx.x * blockDim.x + threadIdx.x) >> 5;
    int lane  = threadIdx.x & 31;
    if (gwarp >= N_NODES) return;
    const float* row = feat + (size_t)gwarp * F_DIM;
    __half* hrow = g_feat_h + (size_t)gwarp * F_DIM;
    float s0 = 0.f, s1 = 0.f;
#pragma unroll
    for (int k = 0; k < 8; k++) {
        int f = k * 32 + lane;
        float v = row[f];
        hrow[f] = __float2half(v);
        s0 += v * __ldg(&wc[f * 2 + 0]);
        s1 += v * __ldg(&wc[f * 2 + 1]);
    }
#pragma unroll
    for (int o = 16; o; o >>= 1) {
        s0 += __shfl_down_sync(0xFFFFFFFFu, s0, o);
        s1 += __shfl_down_sync(0xFFFFFFFFu, s1, o);
    }
    if (lane == 0) {
        g_scores[gwarp * 2 + 0] = s0 + bc[0];
        g_scores[gwarp * 2 + 1] = s1 + bc[1];
    }
}

// ---------------------------------------------------------------------------
// K2: self features -> g_cat cols [0,256) + center scores (4 rows / block)
// ---------------------------------------------------------------------------
__global__ void k_self(const float* __restrict__ feat, const int* __restrict__ nodes,
                       float* __restrict__ out_center) {
    int b = blockIdx.x * 4 + (threadIdx.x >> 6);
    int t = threadIdx.x & 63;
    int node = nodes[b];
    float4 v = *(const float4*)(feat + (size_t)node * F_DIM + 4 * t);
    __nv_bfloat16 h0, h1, h2, h3, l0, l1, l2, l3;
    bf16split(v.x, h0, l0); bf16split(v.y, h1, l1);
    bf16split(v.z, h2, l2); bf16split(v.w, h3, l3);
    size_t base = (size_t)b * CAT_DIM + 4 * t;
    uint2 ph, pl;
    ph.x = pack2(h0, h1); ph.y = pack2(h2, h3);
    pl.x = pack2(l0, l1); pl.y = pack2(l2, l3);
    *(uint2*)(g_cat_hi + base) = ph;
    *(uint2*)(g_cat_lo + base) = pl;
    if (t < 2) out_center[b * 2 + t] = g_scores[node * 2 + t];
}

// ---------------------------------------------------------------------------
// K3: stable top-K=16 by |s1-c| (fp32 scores, warp-shuffle rank — identical
// selection), gather-mean from fp16 copy with LDG.128 (lane owns 8 cols),
// fp32 accumulate, bf16 hi/lo split out. 2 warps/block, 1 b per warp.
// (directly profiled at 22.7us in R13)
// ---------------------------------------------------------------------------
__global__ void k_relsum(const int* __restrict__ nodes,
                         const int* __restrict__ n1, const int* __restrict__ n2,
                         const int* __restrict__ n3) {
    int w    = threadIdx.x >> 5;
    int lane = threadIdx.x & 31;
    int b    = blockIdx.x * 2 + w;
    int r    = blockIdx.y;

    __shared__ int s_sel[2][K_SEL];

    const int* nb = (r == 0 ? n1 : (r == 1 ? n2 : n3)) + (size_t)b * D_DIM;
    int   nv = nb[lane];
    float c  = g_scores[nodes[b] * 2 + 1];
    float d  = fabsf(g_scores[nv * 2 + 1] - c);
    int rank = 0;
#pragma unroll
    for (int j = 0; j < 32; j++) {
        float dj = __shfl_sync(0xFFFFFFFFu, d, j);
        rank += (dj < d) || (dj == d && j < lane);   // stable: matches jax top_k
    }
    if (rank < K_SEL) s_sel[w][rank] = nv;
    __syncwarp();

    int sel[K_SEL];
#pragma unroll
    for (int k = 0; k < K_SEL; k++) sel[k] = s_sel[w][k];

    float acc[8] = {0.f, 0.f, 0.f, 0.f, 0.f, 0.f, 0.f, 0.f};
#pragma unroll
    for (int k = 0; k < K_SEL; k++) {
        uint4 u = *(const uint4*)(g_feat_h + (size_t)sel[k] * F_DIM + lane * 8);
        float2 f0 = __half22float2(*reinterpret_cast<__half2*>(&u.x));
        float2 f1 = __half22float2(*reinterpret_cast<__half2*>(&u.y));
        float2 f2 = __half22float2(*reinterpret_cast<__half2*>(&u.z));
        float2 f3 = __half22float2(*reinterpret_cast<__half2*>(&u.w));
        acc[0] += f0.x; acc[1] += f0.y; acc[2] += f1.x; acc[3] += f1.y;
        acc[4] += f2.x; acc[5] += f2.y; acc[6] += f3.x; acc[7] += f3.y;
    }
    const float s = 1.0f / K_SEL;
    __nv_bfloat16 hh[8], ll[8];
#pragma unroll
    for (int q = 0; q < 8; q++) bf16split(acc[q] * s, hh[q], ll[q]);
    uint4 ph, pl;
    ph.x = pack2(hh[0], hh[1]); ph.y = pack2(hh[2], hh[3]);
    ph.z = pack2(hh[4], hh[5]); ph.w = pack2(hh[6], hh[7]);
    pl.x = pack2(ll[0], ll[1]); pl.y = pack2(ll[2], ll[3]);
    pl.z = pack2(ll[4], ll[5]); pl.w = pack2(ll[6], ll[7]);
    size_t base = ((size_t)r * B_DIM + b) * F_DIM + lane * 8;
    *(uint4*)(g_mean_hi + base) = ph;
    *(uint4*)(g_mean_lo + base) = pl;
}

// ---------------------------------------------------------------------------
// K_prep: bf16-split weights (already [K][N] layout — no transpose)
// ---------------------------------------------------------------------------
__global__ void k_prep(const float* __restrict__ w1, const float* __restrict__ w2,
                       const float* __restrict__ w3, const float* __restrict__ weight) {
    int idx = blockIdx.x * blockDim.x + threadIdx.x;
    const int NW = 3 * F_DIM * E_DIM;   // 98304
    const int NG = CAT_DIM * E_DIM;     // 81920
    if (idx < NW) {
        int r = idx >> 15;
        const float* w = (r == 0 ? w1 : (r == 1 ? w2 : w3));
        float v = w[idx & 32767];
        __nv_bfloat16 h, l; bf16split(v, h, l);
        g_w_hi[idx] = h; g_w_lo[idx] = l;
    } else if (idx < NW + NG) {
        int j = idx - NW;
        float v = weight[j];
        __nv_bfloat16 h, l; bf16split(v, h, l);
        g_wgt_hi[j] = h; g_wgt_lo[j] = l;
    }
}

// ---------------------------------------------------------------------------
// HMMA GEMM, cp.async 2-stage single-sync pipeline (R9/R11-measured, bf16
// 3-term split: Ah*Bh + Ah*Bl + Al*Bh, fp32 accum). 8 warps = 2m x 4n.
// mode 0 (BN=128): blockIdx.y = relation; relu -> bf16 split -> g_cat cols.
// mode 1 (BN=64):  blockIdx.y = n-half;  relu -> out.T
// ---------------------------------------------------------------------------
#define PA 144        // A row pitch bytes (64 bf16 + 16B pad)
#define BM 64
#define SA_SZ (BM * PA)

template<int BN>
__global__ void __launch_bounds__(256, 2)
k_gemm(const __nv_bfloat16* __restrict__ Ah, const __nv_bfloat16* __restrict__ Al,
       const __nv_bfloat16* __restrict__ Bh, const __nv_bfloat16* __restrict__ Bl,
       int K, int mode, float* __restrict__ out) {
    constexpr int JN   = BN / 32;          // 8-col n fragments per warp
    constexpr int PBn  = BN * 2 + 16;      // B row pitch bytes
    constexpr int SBT  = 64 * PBn;
    constexpr int STG  = 2 * SA_SZ + 2 * SBT;

    extern __shared__ char smem[];
    uint32_t sb = smem_u32(smem);

    int tid  = threadIdx.x;
    int lane = tid & 31;
    int warp = tid >> 5;
    int wm   = warp & 1;      // 2 warps along m
    int wn   = warp >> 1;     // 4 warps along n
    int m0   = blockIdx.x * BM;
    int colbase = 0;          // mode 0: g_cat col base; mode 1: out n base

    if (mode == 0) {
        int r = blockIdx.y;
        Ah += (size_t)r * B_DIM * K;
        Al += (size_t)r * B_DIM * K;
        Bh += (size_t)r * K * E_DIM;
        Bl += (size_t)r * K * E_DIM;
        colbase = F_DIM + r * E_DIM;
    } else {
        int nb = blockIdx.y * BN;
        Bh += nb;  Bl += nb;
        colbase = nb;
    }
    const __nv_bfloat16* At_h = Ah + (size_t)m0 * K;
    const __nv_bfloat16* At_l = Al + (size_t)m0 * K;

    uint32_t aoff = (wm * 32 + (lane & 7) + ((lane >> 3) & 1) * 8) * PA + (lane >> 4) * 16;
    uint32_t boff = ((lane & 7) + ((lane >> 3) & 1) * 8) * PBn + (lane >> 4) * 16
                  + wn * (JN * 8) * 2;

    float c[2][JN][4];
#pragma unroll
    for (int i = 0; i < 2; i++)
#pragma unroll
        for (int j = 0; j < JN; j++)
#pragma unroll
            for (int q = 0; q < 4; q++) c[i][j][q] = 0.f;

    const int NC = K >> 6;

    auto stage_load = [&](uint32_t base, int kofs) {
#pragma unroll
        for (int u = tid; u < BM * 8; u += 256) {
            int row = u >> 3, c16 = u & 7;
            size_t go = (size_t)row * K + kofs + c16 * 8;
            uint32_t so = row * PA + c16 * 16;
            cp16(base + so,         At_h + go);
            cp16(base + SA_SZ + so, At_l + go);
        }
#pragma unroll
        for (int u = tid; u < 64 * (BN / 8); u += 256) {
            int row = u / (BN / 8), c16 = u % (BN / 8);
            size_t go = (size_t)(kofs + row) * E_DIM + c16 * 8;
            uint32_t so = row * PBn + c16 * 16;
            cp16(base + 2 * SA_SZ + so,       Bh + go);
            cp16(base + 2 * SA_SZ + SBT + so, Bl + go);
        }
    };

    stage_load(sb, 0);
    CP_COMMIT();

#pragma unroll 1
    for (int ch = 0; ch < NC; ch++) {
        CP_WAIT(0);
        __syncthreads();
        // safe: all warps finished compute(ch-1); buffer (ch+1)&1 == (ch-1)&1 free
        if (ch + 1 < NC) {
            stage_load(sb + ((ch + 1) & 1) * STG, (ch + 1) * 64);
            CP_COMMIT();
        }

        uint32_t base = sb + (ch & 1) * STG;
#pragma unroll
        for (int s = 0; s < 4; s++) {
            uint32_t ah[2][4], al_[2][4];
#pragma unroll
            for (int i = 0; i < 2; i++) {
                ldsm4(ah[i],  base + aoff + i * 16 * PA + 32 * s);
                ldsm4(al_[i], base + SA_SZ + aoff + i * 16 * PA + 32 * s);
            }
            uint32_t bh[JN][2], bl[JN][2];
#pragma unroll
            for (int q = 0; q < JN / 2; q++) {
                uint32_t r4[4];
                ldsm4t(r4, base + 2 * SA_SZ + boff + 16 * s * PBn + q * 32);
                bh[2*q][0] = r4[0]; bh[2*q][1] = r4[1];
                bh[2*q+1][0] = r4[2]; bh[2*q+1][1] = r4[3];
                ldsm4t(r4, base + 2 * SA_SZ + SBT + boff + 16 * s * PBn + q * 32);
                bl[2*q][0] = r4[0]; bl[2*q][1] = r4[1];
                bl[2*q+1][0] = r4[2]; bl[2*q+1][1] = r4[3];
            }
#pragma unroll
            for (int i = 0; i < 2; i++)
#pragma unroll
                for (int j = 0; j < JN; j++) {
                    mma16816(c[i][j], ah[i],  bh[j]);
                    mma16816(c[i][j], ah[i],  bl[j]);
                    mma16816(c[i][j], al_[i], bh[j]);
                }
        }
    }

    int g  = lane >> 2;
    int tg = lane & 3;
#pragma unroll
    for (int i = 0; i < 2; i++) {
#pragma unroll
        for (int j = 0; j < JN; j++) {
            int m = m0 + wm * 32 + i * 16 + g;
            int n = colbase + wn * (JN * 8) + j * 8 + tg * 2;
            float x0 = fmaxf(c[i][j][0], 0.f);
            float x1 = fmaxf(c[i][j][1], 0.f);
            float x2 = fmaxf(c[i][j][2], 0.f);
            float x3 = fmaxf(c[i][j][3], 0.f);
            if (mode == 0) {
                __nv_bfloat16 h0, h1, h2, h3, l0, l1, l2, l3;
                bf16split(x0, h0, l0); bf16split(x1, h1, l1);
                bf16split(x2, h2, l2); bf16split(x3, h3, l3);
                size_t p0 = (size_t)m * CAT_DIM + n;
                size_t p1 = (size_t)(m + 8) * CAT_DIM + n;
                *(uint32_t*)(g_cat_hi + p0) = pack2(h0, h1);
                *(uint32_t*)(g_cat_lo + p0) = pack2(l0, l1);
                *(uint32_t*)(g_cat_hi + p1) = pack2(h2, h3);
                *(uint32_t*)(g_cat_lo + p1) = pack2(l2, l3);
            } else {
                out[(size_t)n * B_DIM + m]           = x0;
                out[(size_t)(n + 1) * B_DIM + m]     = x1;
                out[(size_t)n * B_DIM + m + 8]       = x2;
                out[(size_t)(n + 1) * B_DIM + m + 8] = x3;
            }
        }
    }
}

#define SMEM_G128 (2 * (2 * SA_SZ + 2 * 64 * (128 * 2 + 16)))   // 106496
#define SMEM_G64  (2 * (2 * SA_SZ + 2 * 64 * (64 * 2 + 16)))    // 73728

// ---------------------------------------------------------------------------
extern "C" void kernel_launch(void* const* d_in, const int* in_sizes, int n_in,
                              void* d_out, int out_size) {
    const float* features = (const float*)d_in[0];
    const int*   nodes    = (const int*)d_in[1];
    const int*   n1       = (const int*)d_in[2];
    const int*   n2       = (const int*)d_in[3];
    const int*   n3       = (const int*)d_in[4];
    const float* wc       = (const float*)d_in[5];
    const float* bc       = (const float*)d_in[6];
    const float* w1       = (const float*)d_in[7];
    const float* w2       = (const float*)d_in[8];
    const float* w3       = (const float*)d_in[9];
    const float* weight   = (const float*)d_in[10];

    float* out_combined = (float*)d_out;                 // 128 x 8192
    float* out_center   = (float*)d_out + E_DIM * B_DIM; // 8192 x 2

    static bool attr_done = false;
    static __nv_bfloat16 *p_mean_hi, *p_mean_lo, *p_cat_hi, *p_cat_lo;
    static __nv_bfloat16 *p_w_hi, *p_w_lo, *p_wgt_hi, *p_wgt_lo;
    if (!attr_done) {
        cudaFuncSetAttribute(k_gemm<128>, cudaFuncAttributeMaxDynamicSharedMemorySize, SMEM_G128);
        cudaFuncSetAttribute(k_gemm<64>,  cudaFuncAttributeMaxDynamicSharedMemorySize, SMEM_G64);
        cudaGetSymbolAddress((void**)&p_mean_hi, g_mean_hi);
        cudaGetSymbolAddress((void**)&p_mean_lo, g_mean_lo);
        cudaGetSymbolAddress((void**)&p_cat_hi,  g_cat_hi);
        cudaGetSymbolAddress((void**)&p_cat_lo,  g_cat_lo);
        cudaGetSymbolAddress((void**)&p_w_hi,    g_w_hi);
        cudaGetSymbolAddress((void**)&p_w_lo,    g_w_lo);
        cudaGetSymbolAddress((void**)&p_wgt_hi,  g_wgt_hi);
        cudaGetSymbolAddress((void**)&p_wgt_lo,  g_wgt_lo);
        attr_done = true;
    }

    // weights prep (independent of scores)
    k_prep<<<(3 * F_DIM * E_DIM + CAT_DIM * E_DIM + 255) / 256, 256>>>(w1, w2, w3, weight);

    // scores + fp16 feature copy (R11 scalar form)
    k_scores<<<(N_NODES + 7) / 8, 256>>>(features, wc, bc);

    // self features -> cat + center scores
    k_self<<<B_DIM / 4, 256>>>(features, nodes, out_center);

    // top-K + mean features (fp16 LDG.128 gather, 2 warps/block)
    k_relsum<<<dim3(B_DIM / 2, 3), 64>>>(nodes, n1, n2, n3);

    // relation GEMMs: relu(mean @ w_r) -> cat columns (BN=128, grid 128x3)
    k_gemm<128><<<dim3(B_DIM / BM, 3), 256, SMEM_G128>>>(
        p_mean_hi, p_mean_lo, p_w_hi, p_w_lo, F_DIM, 0, out_combined);

    // final GEMM: relu(cat @ weight).T -> out (BN=64, grid 128x2 = 256 CTAs)
    k_gemm<64><<<dim3(B_DIM / BM, 2), 256, SMEM_G64>>>(
        p_cat_hi, p_cat_lo, p_wgt_hi, p_wgt_lo, CAT_DIM, 1, out_combined);
}

// round 16
// speedup vs baseline: 2.0427x; 1.1899x over previous
#include <cuda_runtime.h>
#include <cuda_fp16.h>
#include <cstdint>

#define N_NODES 100000
#define F_DIM   256
#define E_DIM   128
#define B_DIM   8192
#define D_DIM   32
#define K_SEL   16
#define CAT_DIM 640   // F + 3E

// ---------------------------------------------------------------------------
// Scratch (static device globals — no allocations allowed)
// ---------------------------------------------------------------------------
__device__ __align__(16) float   g_scores[N_NODES * 2];
__device__ __align__(16) __half  g_feat_h[(size_t)N_NODES * F_DIM];  // fp16 features
__device__ __align__(16) __half  g_mean[3ULL * B_DIM * F_DIM];       // [r][m][k]
__device__ __align__(16) __half  g_cat[(size_t)B_DIM * CAT_DIM];     // [m][k]
__device__ __align__(16) __half  g_w[3 * F_DIM * E_DIM];             // [r][k][n]
__device__ __align__(16) __half  g_wgt[CAT_DIM * E_DIM];             // [k][n]

// ---------------------------------------------------------------------------
// helpers
// ---------------------------------------------------------------------------
__device__ __forceinline__ uint32_t smem_u32(const void* p) {
    uint32_t a;
    asm("{ .reg .u64 t; cvta.to.shared.u64 t, %1; cvt.u32.u64 %0, t; }" : "=r"(a) : "l"(p));
    return a;
}
__device__ __forceinline__ uint32_t packh2(float a, float b) {
    __half2 t = __floats2half2_rn(a, b);
    return *reinterpret_cast<uint32_t*>(&t);
}
__device__ __forceinline__ void ldsm4(uint32_t* r, uint32_t addr) {
    asm volatile("ldmatrix.sync.aligned.m8n8.x4.shared.b16 {%0,%1,%2,%3}, [%4];"
                 : "=r"(r[0]), "=r"(r[1]), "=r"(r[2]), "=r"(r[3]) : "r"(addr));
}
__device__ __forceinline__ void ldsm4t(uint32_t* r, uint32_t addr) {
    asm volatile("ldmatrix.sync.aligned.m8n8.x4.trans.shared.b16 {%0,%1,%2,%3}, [%4];"
                 : "=r"(r[0]), "=r"(r[1]), "=r"(r[2]), "=r"(r[3]) : "r"(addr));
}
__device__ __forceinline__ void mma16816(float* c, const uint32_t* a, const uint32_t* b) {
    asm volatile(
        "mma.sync.aligned.m16n8k16.row.col.f32.f16.f16.f32 "
        "{%0,%1,%2,%3}, {%4,%5,%6,%7}, {%8,%9}, {%0,%1,%2,%3};"
        : "+f"(c[0]), "+f"(c[1]), "+f"(c[2]), "+f"(c[3])
        : "r"(a[0]), "r"(a[1]), "r"(a[2]), "r"(a[3]), "r"(b[0]), "r"(b[1]));
}
__device__ __forceinline__ void cp16(uint32_t s, const void* g) {
    asm volatile("cp.async.cg.shared.global [%0], [%1], 16;" :: "r"(s), "l"(g));
}
#define CP_COMMIT() asm volatile("cp.async.commit_group;" ::: "memory")
#define CP_WAIT(n)  asm volatile("cp.async.wait_group %0;" :: "n"(n) : "memory")

// ---------------------------------------------------------------------------
// K1: scores[n] = features[n] @ wc + bc (one warp per node)
//     + fp16 copy of features (R11/R14-measured scalar form)
// ---------------------------------------------------------------------------
__global__ void k_scores(const float* __restrict__ feat, const float* __restrict__ wc,
                         const float* __restrict__ bc) {
    int gwarp = (blockIdx.x * blockDim.x + threadIdx.x) >> 5;
    int lane  = threadIdx.x & 31;
    if (gwarp >= N_NODES) return;
    const float* row = feat + (size_t)gwarp * F_DIM;
    __half* hrow = g_feat_h + (size_t)gwarp * F_DIM;
    float s0 = 0.f, s1 = 0.f;
#pragma unroll
    for (int k = 0; k < 8; k++) {
        int f = k * 32 + lane;
        float v = row[f];
        hrow[f] = __float2half(v);
        s0 += v * __ldg(&wc[f * 2 + 0]);
        s1 += v * __ldg(&wc[f * 2 + 1]);
    }
#pragma unroll
    for (int o = 16; o; o >>= 1) {
        s0 += __shfl_down_sync(0xFFFFFFFFu, s0, o);
        s1 += __shfl_down_sync(0xFFFFFFFFu, s1, o);
    }
    if (lane == 0) {
        g_scores[gwarp * 2 + 0] = s0 + bc[0];
        g_scores[gwarp * 2 + 1] = s1 + bc[1];
    }
}

// ---------------------------------------------------------------------------
// K2: self features -> g_cat cols [0,256) fp16 + center scores (4 rows/block)
// ---------------------------------------------------------------------------
__global__ void k_self(const float* __restrict__ feat, const int* __restrict__ nodes,
                       float* __restrict__ out_center) {
    int b = blockIdx.x * 4 + (threadIdx.x >> 6);
    int t = threadIdx.x & 63;
    int node = nodes[b];
    float4 v = *(const float4*)(feat + (size_t)node * F_DIM + 4 * t);
    uint2 h;
    h.x = packh2(v.x, v.y);
    h.y = packh2(v.z, v.w);
    *(uint2*)(g_cat + (size_t)b * CAT_DIM + 4 * t) = h;
    if (t < 2) out_center[b * 2 + t] = g_scores[node * 2 + t];
}

// ---------------------------------------------------------------------------
// K3: stable top-K=16 by |s1-c| (fp32 scores, warp-shuffle rank — identical
// selection), gather-mean from fp16 copy with LDG.128 (lane owns 8 cols),
// fp32 accumulate, fp16 store to g_mean. 2 warps/block, 1 b per warp.
// (directly profiled at ~23us in R12/R13)
// ---------------------------------------------------------------------------
__global__ void k_relsum(const int* __restrict__ nodes,
                         const int* __restrict__ n1, const int* __restrict__ n2,
                         const int* __restrict__ n3) {
    int w    = threadIdx.x >> 5;
    int lane = threadIdx.x & 31;
    int b    = blockIdx.x * 2 + w;
    int r    = blockIdx.y;

    __shared__ int s_sel[2][K_SEL];

    const int* nb = (r == 0 ? n1 : (r == 1 ? n2 : n3)) + (size_t)b * D_DIM;
    int   nv = nb[lane];
    float c  = g_scores[nodes[b] * 2 + 1];
    float d  = fabsf(g_scores[nv * 2 + 1] - c);
    int rank = 0;
#pragma unroll
    for (int j = 0; j < 32; j++) {
        float dj = __shfl_sync(0xFFFFFFFFu, d, j);
        rank += (dj < d) || (dj == d && j < lane);   // stable: matches jax top_k
    }
    if (rank < K_SEL) s_sel[w][rank] = nv;
    __syncwarp();

    int sel[K_SEL];
#pragma unroll
    for (int k = 0; k < K_SEL; k++) sel[k] = s_sel[w][k];

    float acc[8] = {0.f, 0.f, 0.f, 0.f, 0.f, 0.f, 0.f, 0.f};
#pragma unroll
    for (int k = 0; k < K_SEL; k++) {
        uint4 u = *(const uint4*)(g_feat_h + (size_t)sel[k] * F_DIM + lane * 8);
        float2 f0 = __half22float2(*reinterpret_cast<__half2*>(&u.x));
        float2 f1 = __half22float2(*reinterpret_cast<__half2*>(&u.y));
        float2 f2 = __half22float2(*reinterpret_cast<__half2*>(&u.z));
        float2 f3 = __half22float2(*reinterpret_cast<__half2*>(&u.w));
        acc[0] += f0.x; acc[1] += f0.y; acc[2] += f1.x; acc[3] += f1.y;
        acc[4] += f2.x; acc[5] += f2.y; acc[6] += f3.x; acc[7] += f3.y;
    }
    const float s = 1.0f / K_SEL;
    uint4 h;
    h.x = packh2(acc[0] * s, acc[1] * s);
    h.y = packh2(acc[2] * s, acc[3] * s);
    h.z = packh2(acc[4] * s, acc[5] * s);
    h.w = packh2(acc[6] * s, acc[7] * s);
    *(uint4*)(g_mean + ((size_t)r * B_DIM + b) * F_DIM + lane * 8) = h;
}

// ---------------------------------------------------------------------------
// K_prep: fp16 weights (already [K][N] layout — no transpose)
// ---------------------------------------------------------------------------
__global__ void k_prep(const float* __restrict__ w1, const float* __restrict__ w2,
                       const float* __restrict__ w3, const float* __restrict__ weight) {
    int idx = blockIdx.x * blockDim.x + threadIdx.x;
    const int NW = 3 * F_DIM * E_DIM;   // 98304
    const int NG = CAT_DIM * E_DIM;     // 81920
    if (idx < NW) {
        int r = idx >> 15;
        const float* w = (r == 0 ? w1 : (r == 1 ? w2 : w3));
        g_w[idx] = __float2half(w[idx & 32767]);
    } else if (idx < NW + NG) {
        int j = idx - NW;
        g_wgt[j] = __float2half(weight[j]);
    }
}

// ---------------------------------------------------------------------------
// HMMA GEMM, single-term fp16, cp.async 2-stage single-sync pipeline.
// C[64,BN] tile = A[64,K] @ B[K,BN]; fp32 accum. (R12-measured: ~16us faster
// than the bf16 3-term path.) 8 warps = 2m x 4n; warp tile 32 x (BN/4).
// mode 0 (BN=128): blockIdx.y = relation; relu -> fp16 -> g_cat cols.
// mode 1 (BN=64):  blockIdx.y = n-half;  relu -> fp32 out.T
// ---------------------------------------------------------------------------
#define PA 144        // A row pitch bytes (64 fp16 = 128B + 16 pad)
#define BM 64
#define SA_SZ (BM * PA)

template<int BN>
__global__ void __launch_bounds__(256, 2)
k_gemm(const __half* __restrict__ A, const __half* __restrict__ B,
       int K, int mode, float* __restrict__ out) {
    constexpr int JN   = BN / 32;          // 8-col n fragments per warp
    constexpr int PBn  = BN * 2 + 16;      // B row pitch bytes
    constexpr int SBT  = 64 * PBn;
    constexpr int STG  = SA_SZ + SBT;

    extern __shared__ char smem[];
    uint32_t sb = smem_u32(smem);

    int tid  = threadIdx.x;
    int lane = tid & 31;
    int warp = tid >> 5;
    int wm   = warp & 1;      // 2 warps along m
    int wn   = warp >> 1;     // 4 warps along n
    int m0   = blockIdx.x * BM;
    int colbase = 0;          // mode 0: g_cat col base; mode 1: out n base

    if (mode == 0) {
        int r = blockIdx.y;
        A += (size_t)r * B_DIM * K;
        B += (size_t)r * K * E_DIM;
        colbase = F_DIM + r * E_DIM;
    } else {
        int nb = blockIdx.y * BN;
        B += nb;
        colbase = nb;
    }
    const __half* At = A + (size_t)m0 * K;

    uint32_t aoff = (wm * 32 + (lane & 7) + ((lane >> 3) & 1) * 8) * PA + (lane >> 4) * 16;
    uint32_t boff = ((lane & 7) + ((lane >> 3) & 1) * 8) * PBn + (lane >> 4) * 16
                  + wn * (JN * 8) * 2;

    float c[2][JN][4];
#pragma unroll
    for (int i = 0; i < 2; i++)
#pragma unroll
        for (int j = 0; j < JN; j++)
#pragma unroll
            for (int q = 0; q < 4; q++) c[i][j][q] = 0.f;

    const int NC = K >> 6;

    auto stage_load = [&](uint32_t base, int kofs) {
#pragma unroll
        for (int u = tid; u < BM * 8; u += 256) {
            int row = u >> 3, c16 = u & 7;
            cp16(base + row * PA + c16 * 16, At + (size_t)row * K + kofs + c16 * 8);
        }
#pragma unroll
        for (int u = tid; u < 64 * (BN / 8); u += 256) {
            int row = u / (BN / 8), c16 = u % (BN / 8);
            cp16(base + SA_SZ + row * PBn + c16 * 16,
                 B + (size_t)(kofs + row) * E_DIM + c16 * 8);
        }
    };

    stage_load(sb, 0);
    CP_COMMIT();

#pragma unroll 1
    for (int ch = 0; ch < NC; ch++) {
        CP_WAIT(0);
        __syncthreads();
        // safe: all warps finished compute(ch-1); buffer (ch+1)&1 == (ch-1)&1 free
        if (ch + 1 < NC) {
            stage_load(sb + ((ch + 1) & 1) * STG, (ch + 1) * 64);
            CP_COMMIT();
        }

        uint32_t base = sb + (ch & 1) * STG;
#pragma unroll
        for (int s = 0; s < 4; s++) {
            uint32_t a[2][4];
#pragma unroll
            for (int i = 0; i < 2; i++)
                ldsm4(a[i], base + aoff + i * 16 * PA + 32 * s);
            uint32_t bfr[JN][2];
#pragma unroll
            for (int q = 0; q < JN / 2; q++) {
                uint32_t r4[4];
                ldsm4t(r4, base + SA_SZ + boff + 16 * s * PBn + q * 32);
                bfr[2*q][0] = r4[0]; bfr[2*q][1] = r4[1];
                bfr[2*q+1][0] = r4[2]; bfr[2*q+1][1] = r4[3];
            }
#pragma unroll
            for (int i = 0; i < 2; i++)
#pragma unroll
                for (int j = 0; j < JN; j++)
                    mma16816(c[i][j], a[i], bfr[j]);
        }
    }

    int g  = lane >> 2;
    int tg = lane & 3;
#pragma unroll
    for (int i = 0; i < 2; i++) {
#pragma unroll
        for (int j = 0; j < JN; j++) {
            int m = m0 + wm * 32 + i * 16 + g;
            int n = colbase + wn * (JN * 8) + j * 8 + tg * 2;
            float x0 = fmaxf(c[i][j][0], 0.f);
            float x1 = fmaxf(c[i][j][1], 0.f);
            float x2 = fmaxf(c[i][j][2], 0.f);
            float x3 = fmaxf(c[i][j][3], 0.f);
            if (mode == 0) {
                *(uint32_t*)(g_cat + (size_t)m * CAT_DIM + n)       = packh2(x0, x1);
                *(uint32_t*)(g_cat + (size_t)(m + 8) * CAT_DIM + n) = packh2(x2, x3);
            } else {
                out[(size_t)n * B_DIM + m]           = x0;
                out[(size_t)(n + 1) * B_DIM + m]     = x1;
                out[(size_t)n * B_DIM + m + 8]       = x2;
                out[(size_t)(n + 1) * B_DIM + m + 8] = x3;
            }
        }
    }
}

#define SMEM_G128 (2 * (SA_SZ + 64 * (128 * 2 + 16)))   // 53248
#define SMEM_G64  (2 * (SA_SZ + 64 * (64 * 2 + 16)))    // 36864

// ---------------------------------------------------------------------------
extern "C" void kernel_launch(void* const* d_in, const int* in_sizes, int n_in,
                              void* d_out, int out_size) {
    const float* features = (const float*)d_in[0];
    const int*   nodes    = (const int*)d_in[1];
    const int*   n1       = (const int*)d_in[2];
    const int*   n2       = (const int*)d_in[3];
    const int*   n3       = (const int*)d_in[4];
    const float* wc       = (const float*)d_in[5];
    const float* bc       = (const float*)d_in[6];
    const float* w1       = (const float*)d_in[7];
    const float* w2       = (const float*)d_in[8];
    const float* w3       = (const float*)d_in[9];
    const float* weight   = (const float*)d_in[10];

    float* out_combined = (float*)d_out;                 // 128 x 8192
    float* out_center   = (float*)d_out + E_DIM * B_DIM; // 8192 x 2

    static bool attr_done = false;
    static __half *p_mean, *p_cat, *p_w, *p_wgt;
    if (!attr_done) {
        cudaFuncSetAttribute(k_gemm<128>, cudaFuncAttributeMaxDynamicSharedMemorySize, SMEM_G128);
        cudaFuncSetAttribute(k_gemm<64>,  cudaFuncAttributeMaxDynamicSharedMemorySize, SMEM_G64);
        cudaGetSymbolAddress((void**)&p_mean, g_mean);
        cudaGetSymbolAddress((void**)&p_cat,  g_cat);
        cudaGetSymbolAddress((void**)&p_w,    g_w);
        cudaGetSymbolAddress((void**)&p_wgt,  g_wgt);
        attr_done = true;
    }

    // weights prep (independent of scores)
    k_prep<<<(3 * F_DIM * E_DIM + CAT_DIM * E_DIM + 255) / 256, 256>>>(w1, w2, w3, weight);

    // scores + fp16 feature copy (scalar, measured form)
    k_scores<<<(N_NODES + 7) / 8, 256>>>(features, wc, bc);

    // self features -> cat + center scores
    k_self<<<B_DIM / 4, 256>>>(features, nodes, out_center);

    // top-K + mean features (fp16 LDG.128 gather, 2 warps/block)
    k_relsum<<<dim3(B_DIM / 2, 3), 64>>>(nodes, n1, n2, n3);

    // relation GEMMs: relu(mean @ w_r) -> cat columns (BN=128, grid 128x3)
    k_gemm<128><<<dim3(B_DIM / BM, 3), 256, SMEM_G128>>>(
        p_mean, p_w, F_DIM, 0, out_combined);

    // final GEMM: relu(cat @ weight).T -> out (BN=64, grid 128x2 = 256 CTAs)
    k_gemm<64><<<dim3(B_DIM / BM, 2), 256, SMEM_G64>>>(
        p_cat, p_wgt, CAT_DIM, 1, out_combined);
}

// round 17
// speedup vs baseline: 2.1159x; 1.0358x over previous
#include <cuda_runtime.h>
#include <cuda_fp16.h>
#include <cstdint>

#define N_NODES 100000
#define F_DIM   256
#define E_DIM   128
#define B_DIM   8192
#define D_DIM   32
#define K_SEL   16
#define CAT_DIM 640   // F + 3E

// ---------------------------------------------------------------------------
// Scratch (static device globals — no allocations allowed)
// ---------------------------------------------------------------------------
__device__ __align__(16) float   g_scores[N_NODES * 2];
__device__ __align__(16) __half  g_feat_h[(size_t)N_NODES * F_DIM];  // fp16 features
__device__ __align__(16) __half  g_mean[3ULL * B_DIM * F_DIM];       // [r][m][k]
__device__ __align__(16) __half  g_cat[(size_t)B_DIM * CAT_DIM];     // [m][k]
__device__ __align__(16) __half  g_w[3 * F_DIM * E_DIM];             // [r][k][n]
__device__ __align__(16) __half  g_wgt[CAT_DIM * E_DIM];             // [k][n]

// ---------------------------------------------------------------------------
// helpers
// ---------------------------------------------------------------------------
__device__ __forceinline__ uint32_t smem_u32(const void* p) {
    uint32_t a;
    asm("{ .reg .u64 t; cvta.to.shared.u64 t, %1; cvt.u32.u64 %0, t; }" : "=r"(a) : "l"(p));
    return a;
}
__device__ __forceinline__ uint32_t packh2(float a, float b) {
    __half2 t = __floats2half2_rn(a, b);
    return *reinterpret_cast<uint32_t*>(&t);
}
__device__ __forceinline__ void ldsm4(uint32_t* r, uint32_t addr) {
    asm volatile("ldmatrix.sync.aligned.m8n8.x4.shared.b16 {%0,%1,%2,%3}, [%4];"
                 : "=r"(r[0]), "=r"(r[1]), "=r"(r[2]), "=r"(r[3]) : "r"(addr));
}
__device__ __forceinline__ void ldsm4t(uint32_t* r, uint32_t addr) {
    asm volatile("ldmatrix.sync.aligned.m8n8.x4.trans.shared.b16 {%0,%1,%2,%3}, [%4];"
                 : "=r"(r[0]), "=r"(r[1]), "=r"(r[2]), "=r"(r[3]) : "r"(addr));
}
__device__ __forceinline__ void mma16816(float* c, const uint32_t* a, const uint32_t* b) {
    asm volatile(
        "mma.sync.aligned.m16n8k16.row.col.f32.f16.f16.f32 "
        "{%0,%1,%2,%3}, {%4,%5,%6,%7}, {%8,%9}, {%0,%1,%2,%3};"
        : "+f"(c[0]), "+f"(c[1]), "+f"(c[2]), "+f"(c[3])
        : "r"(a[0]), "r"(a[1]), "r"(a[2]), "r"(a[3]), "r"(b[0]), "r"(b[1]));
}
__device__ __forceinline__ void cp16(uint32_t s, const void* g) {
    asm volatile("cp.async.cg.shared.global [%0], [%1], 16;" :: "r"(s), "l"(g));
}
#define CP_COMMIT() asm volatile("cp.async.commit_group;" ::: "memory")
#define CP_WAIT(n)  asm volatile("cp.async.wait_group %0;" :: "n"(n) : "memory")

// ---------------------------------------------------------------------------
// K1: scores[n] = features[n] @ wc + bc (one warp per node)
//     + fp16 copy of features (measured scalar form)
// ---------------------------------------------------------------------------
__global__ void k_scores(const float* __restrict__ feat, const float* __restrict__ wc,
                         const float* __restrict__ bc) {
    int gwarp = (blockIdx.x * blockDim.x + threadIdx.x) >> 5;
    int lane  = threadIdx.x & 31;
    if (gwarp >= N_NODES) return;
    const float* row = feat + (size_t)gwarp * F_DIM;
    __half* hrow = g_feat_h + (size_t)gwarp * F_DIM;
    float s0 = 0.f, s1 = 0.f;
#pragma unroll
    for (int k = 0; k < 8; k++) {
        int f = k * 32 + lane;
        float v = row[f];
        hrow[f] = __float2half(v);
        s0 += v * __ldg(&wc[f * 2 + 0]);
        s1 += v * __ldg(&wc[f * 2 + 1]);
    }
#pragma unroll
    for (int o = 16; o; o >>= 1) {
        s0 += __shfl_down_sync(0xFFFFFFFFu, s0, o);
        s1 += __shfl_down_sync(0xFFFFFFFFu, s1, o);
    }
    if (lane == 0) {
        g_scores[gwarp * 2 + 0] = s0 + bc[0];
        g_scores[gwarp * 2 + 1] = s1 + bc[1];
    }
}

// ---------------------------------------------------------------------------
// K2: self features -> g_cat cols [0,256) fp16 + center scores (4 rows/block)
// ---------------------------------------------------------------------------
__global__ void k_self(const float* __restrict__ feat, const int* __restrict__ nodes,
                       float* __restrict__ out_center) {
    int b = blockIdx.x * 4 + (threadIdx.x >> 6);
    int t = threadIdx.x & 63;
    int node = nodes[b];
    float4 v = *(const float4*)(feat + (size_t)node * F_DIM + 4 * t);
    uint2 h;
    h.x = packh2(v.x, v.y);
    h.y = packh2(v.z, v.w);
    *(uint2*)(g_cat + (size_t)b * CAT_DIM + 4 * t) = h;
    if (t < 2) out_center[b * 2 + t] = g_scores[node * 2 + t];
}

// ---------------------------------------------------------------------------
// K3: stable top-K=16 by |s1-c| (fp32 scores, warp-shuffle rank — identical
// selection), gather-mean from fp16 copy with LDG.128 (lane owns 8 cols),
// fp32 accumulate, fp16 store. 8 warps/block (256 threads), 1 b per warp.
// ---------------------------------------------------------------------------
__global__ void __launch_bounds__(256)
k_relsum(const int* __restrict__ nodes,
         const int* __restrict__ n1, const int* __restrict__ n2,
         const int* __restrict__ n3) {
    int w    = threadIdx.x >> 5;
    int lane = threadIdx.x & 31;
    int b    = blockIdx.x * 8 + w;
    int r    = blockIdx.y;

    __shared__ int s_sel[8][K_SEL];

    const int* nb = (r == 0 ? n1 : (r == 1 ? n2 : n3)) + (size_t)b * D_DIM;
    int   nv = nb[lane];
    float c  = g_scores[nodes[b] * 2 + 1];
    float d  = fabsf(g_scores[nv * 2 + 1] - c);
    int rank = 0;
#pragma unroll
    for (int j = 0; j < 32; j++) {
        float dj = __shfl_sync(0xFFFFFFFFu, d, j);
        rank += (dj < d) || (dj == d && j < lane);   // stable: matches jax top_k
    }
    if (rank < K_SEL) s_sel[w][rank] = nv;
    __syncwarp();

    int sel[K_SEL];
#pragma unroll
    for (int k = 0; k < K_SEL; k++) sel[k] = s_sel[w][k];

    float acc[8] = {0.f, 0.f, 0.f, 0.f, 0.f, 0.f, 0.f, 0.f};
#pragma unroll
    for (int k = 0; k < K_SEL; k++) {
        uint4 u = *(const uint4*)(g_feat_h + (size_t)sel[k] * F_DIM + lane * 8);
        float2 f0 = __half22float2(*reinterpret_cast<__half2*>(&u.x));
        float2 f1 = __half22float2(*reinterpret_cast<__half2*>(&u.y));
        float2 f2 = __half22float2(*reinterpret_cast<__half2*>(&u.z));
        float2 f3 = __half22float2(*reinterpret_cast<__half2*>(&u.w));
        acc[0] += f0.x; acc[1] += f0.y; acc[2] += f1.x; acc[3] += f1.y;
        acc[4] += f2.x; acc[5] += f2.y; acc[6] += f3.x; acc[7] += f3.y;
    }
    const float s = 1.0f / K_SEL;
    uint4 h;
    h.x = packh2(acc[0] * s, acc[1] * s);
    h.y = packh2(acc[2] * s, acc[3] * s);
    h.z = packh2(acc[4] * s, acc[5] * s);
    h.w = packh2(acc[6] * s, acc[7] * s);
    *(uint4*)(g_mean + ((size_t)r * B_DIM + b) * F_DIM + lane * 8) = h;
}

// ---------------------------------------------------------------------------
// K_prep: fp16 weights (already [K][N] layout — no transpose)
// ---------------------------------------------------------------------------
__global__ void k_prep(const float* __restrict__ w1, const float* __restrict__ w2,
                       const float* __restrict__ w3, const float* __restrict__ weight) {
    int idx = blockIdx.x * blockDim.x + threadIdx.x;
    const int NW = 3 * F_DIM * E_DIM;   // 98304
    const int NG = CAT_DIM * E_DIM;     // 81920
    if (idx < NW) {
        int r = idx >> 15;
        const float* w = (r == 0 ? w1 : (r == 1 ? w2 : w3));
        g_w[idx] = __float2half(w[idx & 32767]);
    } else if (idx < NW + NG) {
        int j = idx - NW;
        g_wgt[j] = __float2half(weight[j]);
    }
}

// ---------------------------------------------------------------------------
// HMMA GEMM, single-term fp16, cp.async 3-stage pipeline (wait(1): one load
// always in flight behind compute). C[64,BN] = A[64,K] @ B[K,BN]; fp32 accum.
// 8 warps = 2m x 4n; warp tile 32 x (BN/4).
// mode 0 (BN=128): blockIdx.y = relation; relu -> fp16 -> g_cat cols.
// mode 1 (BN=64):  blockIdx.y = n-half;  relu -> fp32 out.T
// ---------------------------------------------------------------------------
#define PA 144        // A row pitch bytes (64 fp16 = 128B + 16 pad)
#define BM 64
#define SA_SZ (BM * PA)

template<int BN>
__global__ void __launch_bounds__(256, 2)
k_gemm(const __half* __restrict__ A, const __half* __restrict__ B,
       int K, int mode, float* __restrict__ out) {
    constexpr int JN   = BN / 32;          // 8-col n fragments per warp
    constexpr int PBn  = BN * 2 + 16;      // B row pitch bytes
    constexpr int SBT  = 64 * PBn;
    constexpr int STG  = SA_SZ + SBT;

    extern __shared__ char smem[];
    uint32_t sb = smem_u32(smem);

    int tid  = threadIdx.x;
    int lane = tid & 31;
    int warp = tid >> 5;
    int wm   = warp & 1;      // 2 warps along m
    int wn   = warp >> 1;     // 4 warps along n
    int m0   = blockIdx.x * BM;
    int colbase = 0;          // mode 0: g_cat col base; mode 1: out n base

    if (mode == 0) {
        int r = blockIdx.y;
        A += (size_t)r * B_DIM * K;
        B += (size_t)r * K * E_DIM;
        colbase = F_DIM + r * E_DIM;
    } else {
        int nb = blockIdx.y * BN;
        B += nb;
        colbase = nb;
    }
    const __half* At = A + (size_t)m0 * K;

    uint32_t aoff = (wm * 32 + (lane & 7) + ((lane >> 3) & 1) * 8) * PA + (lane >> 4) * 16;
    uint32_t boff = ((lane & 7) + ((lane >> 3) & 1) * 8) * PBn + (lane >> 4) * 16
                  + wn * (JN * 8) * 2;

    float c[2][JN][4];
#pragma unroll
    for (int i = 0; i < 2; i++)
#pragma unroll
        for (int j = 0; j < JN; j++)
#pragma unroll
            for (int q = 0; q < 4; q++) c[i][j][q] = 0.f;

    const int NC = K >> 6;

    auto stage_load = [&](uint32_t base, int kofs) {
#pragma unroll
        for (int u = tid; u < BM * 8; u += 256) {
            int row = u >> 3, c16 = u & 7;
            cp16(base + row * PA + c16 * 16, At + (size_t)row * K + kofs + c16 * 8);
        }
#pragma unroll
        for (int u = tid; u < 64 * (BN / 8); u += 256) {
            int row = u / (BN / 8), c16 = u % (BN / 8);
            cp16(base + SA_SZ + row * PBn + c16 * 16,
                 B + (size_t)(kofs + row) * E_DIM + c16 * 8);
        }
    };

    // prefetch stages 0 and 1
    stage_load(sb, 0);
    CP_COMMIT();
    stage_load(sb + STG, 64);
    CP_COMMIT();

    int buf = 0;  // ch % 3
#pragma unroll 1
    for (int ch = 0; ch < NC; ch++) {
        if (ch < NC - 1) { CP_WAIT(1); } else { CP_WAIT(0); }
        __syncthreads();
        // buffer (ch+2)%3 was consumed at compute(ch-1), which precedes this sync
        if (ch + 2 < NC) {
            int nbuf = buf + 2; if (nbuf >= 3) nbuf -= 3;
            stage_load(sb + nbuf * STG, (ch + 2) * 64);
            CP_COMMIT();
        }

        uint32_t base = sb + buf * STG;
#pragma unroll
        for (int s = 0; s < 4; s++) {
            uint32_t a[2][4];
#pragma unroll
            for (int i = 0; i < 2; i++)
                ldsm4(a[i], base + aoff + i * 16 * PA + 32 * s);
            uint32_t bfr[JN][2];
#pragma unroll
            for (int q = 0; q < JN / 2; q++) {
                uint32_t r4[4];
                ldsm4t(r4, base + SA_SZ + boff + 16 * s * PBn + q * 32);
                bfr[2*q][0] = r4[0]; bfr[2*q][1] = r4[1];
                bfr[2*q+1][0] = r4[2]; bfr[2*q+1][1] = r4[3];
            }
#pragma unroll
            for (int i = 0; i < 2; i++)
#pragma unroll
                for (int j = 0; j < JN; j++)
                    mma16816(c[i][j], a[i], bfr[j]);
        }
        buf++; if (buf == 3) buf = 0;
    }

    int g  = lane >> 2;
    int tg = lane & 3;
#pragma unroll
    for (int i = 0; i < 2; i++) {
#pragma unroll
        for (int j = 0; j < JN; j++) {
            int m = m0 + wm * 32 + i * 16 + g;
            int n = colbase + wn * (JN * 8) + j * 8 + tg * 2;
            float x0 = fmaxf(c[i][j][0], 0.f);
            float x1 = fmaxf(c[i][j][1], 0.f);
            float x2 = fmaxf(c[i][j][2], 0.f);
            float x3 = fmaxf(c[i][j][3], 0.f);
            if (mode == 0) {
                *(uint32_t*)(g_cat + (size_t)m * CAT_DIM + n)       = packh2(x0, x1);
                *(uint32_t*)(g_cat + (size_t)(m + 8) * CAT_DIM + n) = packh2(x2, x3);
            } else {
                out[(size_t)n * B_DIM + m]           = x0;
                out[(size_t)(n + 1) * B_DIM + m]     = x1;
                out[(size_t)n * B_DIM + m + 8]       = x2;
                out[(size_t)(n + 1) * B_DIM + m + 8] = x3;
            }
        }
    }
}

#define SMEM_G128 (3 * (SA_SZ + 64 * (128 * 2 + 16)))   // 79872
#define SMEM_G64  (3 * (SA_SZ + 64 * (64 * 2 + 16)))    // 55296

// ---------------------------------------------------------------------------
extern "C" void kernel_launch(void* const* d_in, const int* in_sizes, int n_in,
                              void* d_out, int out_size) {
    const float* features = (const float*)d_in[0];
    const int*   nodes    = (const int*)d_in[1];
    const int*   n1       = (const int*)d_in[2];
    const int*   n2       = (const int*)d_in[3];
    const int*   n3       = (const int*)d_in[4];
    const float* wc       = (const float*)d_in[5];
    const float* bc       = (const float*)d_in[6];
    const float* w1       = (const float*)d_in[7];
    const float* w2       = (const float*)d_in[8];
    const float* w3       = (const float*)d_in[9];
    const float* weight   = (const float*)d_in[10];

    float* out_combined = (float*)d_out;                 // 128 x 8192
    float* out_center   = (float*)d_out + E_DIM * B_DIM; // 8192 x 2

    static bool attr_done = false;
    static __half *p_mean, *p_cat, *p_w, *p_wgt;
    if (!attr_done) {
        cudaFuncSetAttribute(k_gemm<128>, cudaFuncAttributeMaxDynamicSharedMemorySize, SMEM_G128);
        cudaFuncSetAttribute(k_gemm<64>,  cudaFuncAttributeMaxDynamicSharedMemorySize, SMEM_G64);
        cudaGetSymbolAddress((void**)&p_mean, g_mean);
        cudaGetSymbolAddress((void**)&p_cat,  g_cat);
        cudaGetSymbolAddress((void**)&p_w,    g_w);
        cudaGetSymbolAddress((void**)&p_wgt,  g_wgt);
        attr_done = true;
    }

    // weights prep (independent of scores)
    k_prep<<<(3 * F_DIM * E_DIM + CAT_DIM * E_DIM + 255) / 256, 256>>>(w1, w2, w3, weight);

    // scores + fp16 feature copy
    k_scores<<<(N_NODES + 7) / 8, 256>>>(features, wc, bc);

    // self features -> cat + center scores
    k_self<<<B_DIM / 4, 256>>>(features, nodes, out_center);

    // top-K + mean features (8 warps/block)
    k_relsum<<<dim3(B_DIM / 8, 3), 256>>>(nodes, n1, n2, n3);

    // relation GEMMs: relu(mean @ w_r) -> cat columns (BN=128, grid 128x3)
    k_gemm<128><<<dim3(B_DIM / BM, 3), 256, SMEM_G128>>>(
        p_mean, p_w, F_DIM, 0, out_combined);

    // final GEMM: relu(cat @ weight).T -> out (BN=64, grid 128x2 = 256 CTAs)
    k_gemm<64><<<dim3(B_DIM / BM, 2), 256, SMEM_G64>>>(
        p_cat, p_wgt, CAT_DIM, 1, out_combined);
}